// round 9
// baseline (speedup 1.0000x reference)
#include <cuda_runtime.h>
#include <cuda_fp16.h>
#include <cstdint>
#include <cstddef>

#define NUSERS 100000
#define NITEMS 100000
#define DIN 128
#define DOUT 128
#define NSUP 5
#define NEDGE 500000
#define MTILES ((NUSERS + 127) / 128)
#define NBINS (2 * NSUP * NUSERS)
#define NCHUNK ((NBINS + 1023) / 1024)
#define TOTE (2 * NSUP * NEDGE)

// ---------------------------------------------------------------------------
// Device scratch
// ---------------------------------------------------------------------------
__device__ __half g_Wn[NSUP][DOUT * DIN];              // n-major: [s][n*128 + k]
__device__ __half g_Uh[(size_t)NUSERS * 128];
__device__ __half g_Ih[(size_t)NITEMS * 128];
__device__ __half g_Gh[2][NSUP][(size_t)NUSERS * 128]; // 256 MB gathered A
__device__ int g_cnt[NBINS];
__device__ int g_off[NBINS + 1];
__device__ int g_blksum[1024];
__device__ int2 g_edges[TOTE];

// ---------------------------------------------------------------------------
// Cumulative weight -> fp16, n-major.  weight layout [k][n][s]
// ---------------------------------------------------------------------------
__global__ void wcum_kernel(const float* __restrict__ w) {
    int k = blockIdx.x;
    int n = threadIdx.x;
    const float* p = w + ((size_t)k * DOUT + n) * NSUP;
    float acc = 0.f;
#pragma unroll
    for (int s = 0; s < NSUP; s++) {
        acc += p[s];
        g_Wn[s][n * DIN + k] = __float2half_rn(acc);
    }
}

// ---------------------------------------------------------------------------
// Convert fp32 inputs to fp16.
// ---------------------------------------------------------------------------
__global__ void cvt_kernel(const float* __restrict__ U, const float* __restrict__ It) {
    const int per = NUSERS * 128 / 4;
    int i = blockIdx.x * 256 + threadIdx.x;
    if (i >= 2 * per) return;
    int side = (i >= per) ? 1 : 0;
    int j = i - side * per;
    float4 v = __ldcs((const float4*)(side ? It : U) + j);
    __half* dst = side ? g_Ih : g_Uh;
    uint2 o;
    __half2 h0 = __floats2half2_rn(v.x, v.y);
    __half2 h1 = __floats2half2_rn(v.z, v.w);
    o.x = *(uint32_t*)&h0;
    o.y = *(uint32_t*)&h1;
    __stcs((uint2*)dst + j, o);
}

// ---------------------------------------------------------------------------
// CSR build
// ---------------------------------------------------------------------------
__global__ void zero_kernel() {
    int i = blockIdx.x * 256 + threadIdx.x;
    if (i < NBINS) g_cnt[i] = 0;
}

__global__ void hist_kernel(const int* __restrict__ u_rows,
                            const int* __restrict__ i_rows) {
    int e = blockIdx.x * 256 + threadIdx.x;
    if (e >= TOTE) return;
    int side = (e >= NSUP * NEDGE) ? 1 : 0;
    int ee = e - side * NSUP * NEDGE;
    const int* rows = side ? i_rows : u_rows;
    int s = ee / NEDGE;
    int bin = (side * NSUP + s) * NUSERS + __ldg(&rows[ee]);
    atomicAdd(&g_cnt[bin], 1);
}

__global__ __launch_bounds__(256) void scan1_kernel() {
    __shared__ int s0[256], s1[256];
    int b = blockIdx.x, tid = threadIdx.x;
    int base = b * 1024 + tid * 4;
    int v[4];
#pragma unroll
    for (int j = 0; j < 4; j++) {
        int idx = base + j;
        v[j] = (idx < NBINS) ? g_cnt[idx] : 0;
    }
    int tsum = v[0] + v[1] + v[2] + v[3];
    s0[tid] = tsum;
    __syncthreads();
    int* src = s0;
    int* dst = s1;
#pragma unroll
    for (int o = 1; o < 256; o <<= 1) {
        int x = src[tid];
        if (tid >= o) x += src[tid - o];
        __syncthreads();
        dst[tid] = x;
        __syncthreads();
        int* tmp = src; src = dst; dst = tmp;
    }
    int run = (tid == 0) ? 0 : src[tid - 1];
#pragma unroll
    for (int j = 0; j < 4; j++) {
        int idx = base + j;
        if (idx < NBINS) g_off[idx] = run;
        run += v[j];
    }
    if (tid == 255) g_blksum[b] = src[255];
}

__global__ __launch_bounds__(1024) void scan2_kernel() {
    __shared__ int s0[1024], s1[1024];
    int tid = threadIdx.x;
    s0[tid] = (tid < NCHUNK) ? g_blksum[tid] : 0;
    __syncthreads();
    int* src = s0;
    int* dst = s1;
#pragma unroll
    for (int o = 1; o < 1024; o <<= 1) {
        int x = src[tid];
        if (tid >= o) x += src[tid - o];
        __syncthreads();
        dst[tid] = x;
        __syncthreads();
        int* tmp = src; src = dst; dst = tmp;
    }
    int excl = (tid == 0) ? 0 : src[tid - 1];
    if (tid < NCHUNK) g_blksum[tid] = excl;
    if (tid == 0) g_off[NBINS] = TOTE;
}

__global__ __launch_bounds__(256) void scan3_kernel() {
    int b = blockIdx.x;
    int add = g_blksum[b];
#pragma unroll
    for (int j = 0; j < 4; j++) {
        int idx = b * 1024 + threadIdx.x + 256 * j;
        if (idx < NBINS) {
            int o = g_off[idx] + add;
            g_off[idx] = o;
            g_cnt[idx] = o;
        }
    }
}

__global__ void scatter_kernel(const int* __restrict__ u_rows,
                               const int* __restrict__ u_cols,
                               const float* __restrict__ u_vals,
                               const int* __restrict__ i_rows,
                               const int* __restrict__ i_cols,
                               const float* __restrict__ i_vals) {
    int e = blockIdx.x * 256 + threadIdx.x;
    if (e >= TOTE) return;
    int side = (e >= NSUP * NEDGE) ? 1 : 0;
    int ee = e - side * NSUP * NEDGE;
    const int* rows = side ? i_rows : u_rows;
    const int* cols = side ? i_cols : u_cols;
    const float* vals = side ? i_vals : u_vals;
    int s = ee / NEDGE;
    int bin = (side * NSUP + s) * NUSERS + __ldg(&rows[ee]);
    int pos = atomicAdd(&g_cnt[bin], 1);
    g_edges[pos] = make_int2(__ldg(&cols[ee]), __float_as_int(__ldg(&vals[ee])));
}

// ---------------------------------------------------------------------------
// Atomic-free gather SpMM, one side per launch: warp per row.
// ---------------------------------------------------------------------------
__global__ __launch_bounds__(256) void gather_kernel(int side) {
    int row = (int)((blockIdx.x * 256u + threadIdx.x) >> 5);
    if (row >= NUSERS) return;
    int lane = threadIdx.x & 31;
    const uint2* src = (const uint2*)(side == 0 ? g_Ih : g_Uh);

#pragma unroll
    for (int s = 0; s < NSUP; s++) {
        int bin = (side * NSUP + s) * NUSERS + row;
        int e0 = __ldg(&g_off[bin]);
        int e1 = __ldg(&g_off[bin + 1]);
        float4 acc = make_float4(0.f, 0.f, 0.f, 0.f);
        int e = e0;
        for (; e + 2 <= e1; e += 2) {
            int2 p0 = __ldcs(&g_edges[e]);
            int2 p1 = __ldcs(&g_edges[e + 1]);
            uint2 x0 = __ldg(&src[(size_t)p0.x * 32 + lane]);
            uint2 x1 = __ldg(&src[(size_t)p1.x * 32 + lane]);
            float v0 = __int_as_float(p0.y);
            float v1 = __int_as_float(p1.y);
            float2 a0 = __half22float2(*(__half2*)&x0.x);
            float2 b0 = __half22float2(*(__half2*)&x0.y);
            float2 a1 = __half22float2(*(__half2*)&x1.x);
            float2 b1 = __half22float2(*(__half2*)&x1.y);
            acc.x += v0 * a0.x + v1 * a1.x;
            acc.y += v0 * a0.y + v1 * a1.y;
            acc.z += v0 * b0.x + v1 * b1.x;
            acc.w += v0 * b0.y + v1 * b1.y;
        }
        if (e < e1) {
            int2 p = __ldcs(&g_edges[e]);
            float v = __int_as_float(p.y);
            uint2 x = __ldg(&src[(size_t)p.x * 32 + lane]);
            float2 a = __half22float2(*(__half2*)&x.x);
            float2 b = __half22float2(*(__half2*)&x.y);
            acc.x += v * a.x;
            acc.y += v * a.y;
            acc.z += v * b.x;
            acc.w += v * b.y;
        }
        __half2 o0 = __floats2half2_rn(acc.x, acc.y);
        __half2 o1 = __floats2half2_rn(acc.z, acc.w);
        uint2 o;
        o.x = *(uint32_t*)&o0;
        o.y = *(uint32_t*)&o1;
        __stcs((uint2*)(g_Gh[side][s] + (size_t)row * 128) + lane, o);
    }
}

// ---------------------------------------------------------------------------
// fp16 ldmatrix tensor GEMM, K = 640, one side per launch.
// ---------------------------------------------------------------------------
#define RSTR 144
#define BUFB (128 * RSTR)
#define GT_TOTAL (4 * BUFB)
#define NCHUNKS 10

__device__ __forceinline__ uint32_t smem_u32(const void* p) {
    uint32_t a;
    asm("{ .reg .u64 t; cvta.to.shared.u64 t, %1; cvt.u32.u64 %0, t; }" : "=r"(a) : "l"(p));
    return a;
}
__device__ __forceinline__ void cp16(void* sdst, const void* gsrc) {
    unsigned u = (unsigned)__cvta_generic_to_shared(sdst);
    asm volatile("cp.async.cg.shared.global [%0], [%1], 16;" :: "r"(u), "l"(gsrc));
}
#define LDSM_X4(r, addr)                                                       \
    asm volatile("ldmatrix.sync.aligned.m8n8.x4.shared.b16 {%0,%1,%2,%3}, [%4];" \
                 : "=r"((r)[0]), "=r"((r)[1]), "=r"((r)[2]), "=r"((r)[3])       \
                 : "r"(addr))
#define MMA_F16(c, a, b0, b1)                                                  \
    asm volatile(                                                              \
        "mma.sync.aligned.m16n8k16.row.col.f32.f16.f16.f32 "                  \
        "{%0,%1,%2,%3}, {%4,%5,%6,%7}, {%8,%9}, {%0,%1,%2,%3};"               \
        : "+f"(c[0]), "+f"(c[1]), "+f"(c[2]), "+f"(c[3])                       \
        : "r"(a[0]), "r"(a[1]), "r"(a[2]), "r"(a[3]), "r"(b0), "r"(b1))

__global__ __launch_bounds__(256, 2) void gemm_kernel(float* __restrict__ out, int side) {
    extern __shared__ __align__(16) char smem[];
    const int row0 = blockIdx.x * 128;
    const uint32_t sb = smem_u32(smem);

    const int t = threadIdx.x;
    const int wid = t >> 5;
    const int lane = t & 31;
    const int gid = lane >> 2;
    const int tig = lane & 3;
    const int wm = (wid & 3) * 32;
    const int wn = (wid >> 2) * 64;

    const uint32_t aRowByte = (uint32_t)(wm + (lane & 15)) * RSTR + (lane >> 4) * 16;
    const uint32_t bRowByte = (uint32_t)(wn + (lane >> 4) * 8 + (lane & 7)) * RSTR +
                              ((lane >> 3) & 1) * 16;

    float c[2][8][4];
#pragma unroll
    for (int mt = 0; mt < 2; mt++)
#pragma unroll
        for (int nt = 0; nt < 8; nt++)
#pragma unroll
            for (int i = 0; i < 4; i++) c[mt][nt][i] = 0.f;

    auto copy_chunk = [&](int cidx, int b) {
        int s = cidx >> 1;
        int kh = (cidx & 1) * 64;
        const __half* Asrc = g_Gh[side][s] + kh;
        const __half* Bsrc = g_Wn[s] + kh;
        char* sa = smem + b * BUFB;
        char* sbuf = smem + (2 + b) * BUFB;
#pragma unroll
        for (int i = 0; i < 4; i++) {
            int q = t + 256 * i;
            int row = q >> 3;
            int c16 = (q & 7) * 16;
            int gr = row0 + row;
            if (gr > NUSERS - 1) gr = NUSERS - 1;
            cp16(sa + row * RSTR + c16, Asrc + (size_t)gr * 128 + (c16 >> 1));
            cp16(sbuf + row * RSTR + c16, Bsrc + (size_t)row * 128 + (c16 >> 1));
        }
        asm volatile("cp.async.commit_group;" ::: "memory");
    };

    copy_chunk(0, 0);
    int buf = 0;

#pragma unroll 1
    for (int cc = 0; cc < NCHUNKS; cc++) {
        if (cc + 1 < NCHUNKS) {
            copy_chunk(cc + 1, buf ^ 1);
            asm volatile("cp.async.wait_group 1;" ::: "memory");
        } else {
            asm volatile("cp.async.wait_group 0;" ::: "memory");
        }
        __syncthreads();

        const uint32_t aBase = sb + buf * BUFB + aRowByte;
        const uint32_t bBase = sb + (2 + buf) * BUFB + bRowByte;
#pragma unroll
        for (int ks = 0; ks < 4; ks++) {
            uint32_t a[2][4], bf[4][4];
#pragma unroll
            for (int mt = 0; mt < 2; mt++)
                LDSM_X4(a[mt], aBase + mt * (16 * RSTR) + ks * 32);
#pragma unroll
            for (int nt2 = 0; nt2 < 4; nt2++)
                LDSM_X4(bf[nt2], bBase + nt2 * (16 * RSTR) + ks * 32);
#pragma unroll
            for (int mt = 0; mt < 2; mt++)
#pragma unroll
                for (int nt = 0; nt < 8; nt++) {
                    int nt2 = nt >> 1, sub = (nt & 1) * 2;
                    MMA_F16(c[mt][nt], a[mt], bf[nt2][sub], bf[nt2][sub + 1]);
                }
        }
        buf ^= 1;
        __syncthreads();
    }

    float* O = out + (size_t)side * NUSERS * 128;
#pragma unroll
    for (int mt = 0; mt < 2; mt++) {
        int r0 = row0 + wm + mt * 16 + gid;
        int r1 = r0 + 8;
#pragma unroll
        for (int nt = 0; nt < 8; nt++) {
            int cg = wn + nt * 8 + tig * 2;
            if (r0 < NUSERS)
                *(float2*)&O[(size_t)r0 * 128 + cg] =
                    make_float2(fmaxf(c[mt][nt][0], 0.f), fmaxf(c[mt][nt][1], 0.f));
            if (r1 < NUSERS)
                *(float2*)&O[(size_t)r1 * 128 + cg] =
                    make_float2(fmaxf(c[mt][nt][2], 0.f), fmaxf(c[mt][nt][3], 0.f));
        }
    }
}

// ---------------------------------------------------------------------------
// kernel_launch — forked-stream pipeline (capturable fork/join via events).
// Streams/events created once on the first (non-captured) correctness call.
// ---------------------------------------------------------------------------
extern "C" void kernel_launch(void* const* d_in, const int* in_sizes, int n_in,
                              void* d_out, int out_size) {
    const float* U = (const float*)d_in[0];
    const float* It = (const float*)d_in[1];
    const float* W = (const float*)d_in[2];
    const int* u_rows = (const int*)d_in[3];
    const int* u_cols = (const int*)d_in[4];
    const float* u_vals = (const float*)d_in[5];
    const int* i_rows = (const int*)d_in[6];
    const int* i_cols = (const int*)d_in[7];
    const float* i_vals = (const float*)d_in[8];
    float* out = (float*)d_out;

    static cudaStream_t sPrep = nullptr, sGemm = nullptr;
    static cudaEvent_t evRoot = nullptr, evPrep = nullptr, evG0 = nullptr, evGemm0 = nullptr;
    static bool smemSet = false;
    if (!sPrep) {
        cudaStreamCreateWithFlags(&sPrep, cudaStreamNonBlocking);
        cudaStreamCreateWithFlags(&sGemm, cudaStreamNonBlocking);
        cudaEventCreateWithFlags(&evRoot, cudaEventDisableTiming);
        cudaEventCreateWithFlags(&evPrep, cudaEventDisableTiming);
        cudaEventCreateWithFlags(&evG0, cudaEventDisableTiming);
        cudaEventCreateWithFlags(&evGemm0, cudaEventDisableTiming);
    }
    if (!smemSet) {
        cudaFuncSetAttribute(gemm_kernel, cudaFuncAttributeMaxDynamicSharedMemorySize, GT_TOTAL);
        smemSet = true;
    }

    const int eb = (TOTE + 255) / 256;
    const int gb = (NUSERS * 32 + 255) / 256;

    // fork: prep stream does wcum + cvt while main builds CSR
    cudaEventRecord(evRoot, 0);
    cudaStreamWaitEvent(sPrep, evRoot, 0);
    wcum_kernel<<<DIN, DOUT, 0, sPrep>>>(W);
    cvt_kernel<<<(2 * NUSERS * 128 / 4 + 255) / 256, 256, 0, sPrep>>>(U, It);
    cudaEventRecord(evPrep, sPrep);

    // main: CSR chain
    zero_kernel<<<(NBINS + 255) / 256, 256>>>();
    hist_kernel<<<eb, 256>>>(u_rows, i_rows);
    scan1_kernel<<<NCHUNK, 256>>>();
    scan2_kernel<<<1, 1024>>>();
    scan3_kernel<<<NCHUNK, 256>>>();
    scatter_kernel<<<eb, 256>>>(u_rows, u_cols, u_vals, i_rows, i_cols, i_vals);

    // join prep (cvt needed by gather, wcum by gemm)
    cudaStreamWaitEvent(0, evPrep, 0);

    // gather side 0, then gemm0 (stream sGemm) overlapped with gather side 1
    gather_kernel<<<gb, 256>>>(0);
    cudaEventRecord(evG0, 0);
    cudaStreamWaitEvent(sGemm, evG0, 0);
    gemm_kernel<<<MTILES, 256, GT_TOTAL, sGemm>>>(out, 0);
    cudaEventRecord(evGemm0, sGemm);

    gather_kernel<<<gb, 256>>>(1);
    gemm_kernel<<<MTILES, 256, GT_TOTAL>>>(out, 1);

    // join gemm0 back to the origin stream
    cudaStreamWaitEvent(0, evGemm0, 0);
}

// round 13
// speedup vs baseline: 1.0223x; 1.0223x over previous
#include <cuda_runtime.h>
#include <cuda_fp16.h>
#include <cstdint>
#include <cstddef>

#define NUSERS 100000
#define NITEMS 100000
#define DIN 128
#define DOUT 128
#define NSUP 5
#define NEDGE 500000
#define MTILES ((NUSERS + 127) / 128)
#define NBINS (2 * NSUP * NUSERS)
#define NCHUNK ((NBINS + 1023) / 1024)     // 977
#define TOTE (2 * NSUP * NEDGE)

// ---------------------------------------------------------------------------
// Device scratch
// ---------------------------------------------------------------------------
__device__ __half g_Wn[NSUP][DOUT * DIN];              // n-major: [s][n*128 + k]
__device__ __half g_Uh[(size_t)NUSERS * 128];
__device__ __half g_Ih[(size_t)NITEMS * 128];
__device__ __half g_Gh[2][NSUP][(size_t)NUSERS * 128]; // 256 MB gathered A
__device__ int g_cnt[NBINS];
__device__ int g_off[NBINS + 1];
__device__ int g_blksum[1024];
__device__ int2 g_edges[TOTE];

// ---------------------------------------------------------------------------
// prep: fp32->fp16 input convert + cumulative-weight fp16 repack + cnt zero.
// grid 25000 x 256 covers all three jobs.
// ---------------------------------------------------------------------------
__global__ void prep_kernel(const float* __restrict__ U, const float* __restrict__ It,
                            const float* __restrict__ w) {
    const int per = NUSERS * 128 / 4;
    int i = blockIdx.x * 256 + threadIdx.x;

    if (i < 2 * per) {  // cvt
        int side = (i >= per) ? 1 : 0;
        int j = i - side * per;
        float4 v = __ldcs((const float4*)(side ? It : U) + j);
        __half* dst = side ? g_Ih : g_Uh;
        uint2 o;
        __half2 h0 = __floats2half2_rn(v.x, v.y);
        __half2 h1 = __floats2half2_rn(v.z, v.w);
        o.x = *(uint32_t*)&h0;
        o.y = *(uint32_t*)&h1;
        __stcs((uint2*)dst + j, o);
    }
    if (i < NBINS) g_cnt[i] = 0;  // zero histogram

    if (blockIdx.x < 64) {  // wcum: 2 k-rows per block
        int k = blockIdx.x * 2 + (threadIdx.x >> 7);
        int n = threadIdx.x & 127;
        const float* p = w + ((size_t)k * DOUT + n) * NSUP;
        float acc = 0.f;
#pragma unroll
        for (int s = 0; s < NSUP; s++) {
            acc += p[s];
            g_Wn[s][n * DIN + k] = __float2half_rn(acc);
        }
    }
}

// ---------------------------------------------------------------------------
// CSR build: hist -> scan1 -> scan23 -> scatter
// bin = (side*NSUP + s)*NUSERS + row
// ---------------------------------------------------------------------------
__global__ void hist_kernel(const int* __restrict__ u_rows,
                            const int* __restrict__ i_rows) {
    int e = blockIdx.x * 256 + threadIdx.x;
    if (e >= TOTE) return;
    int side = (e >= NSUP * NEDGE) ? 1 : 0;
    int ee = e - side * NSUP * NEDGE;
    const int* rows = side ? i_rows : u_rows;
    int s = ee / NEDGE;
    int bin = (side * NSUP + s) * NUSERS + __ldg(&rows[ee]);
    atomicAdd(&g_cnt[bin], 1);
}

__global__ __launch_bounds__(256) void scan1_kernel() {
    __shared__ int s0[256], s1[256];
    int b = blockIdx.x, tid = threadIdx.x;
    int base = b * 1024 + tid * 4;
    int v[4];
#pragma unroll
    for (int j = 0; j < 4; j++) {
        int idx = base + j;
        v[j] = (idx < NBINS) ? g_cnt[idx] : 0;
    }
    int tsum = v[0] + v[1] + v[2] + v[3];
    s0[tid] = tsum;
    __syncthreads();
    int* src = s0;
    int* dst = s1;
#pragma unroll
    for (int o = 1; o < 256; o <<= 1) {
        int x = src[tid];
        if (tid >= o) x += src[tid - o];
        __syncthreads();
        dst[tid] = x;
        __syncthreads();
        int* tmp = src; src = dst; dst = tmp;
    }
    int run = (tid == 0) ? 0 : src[tid - 1];
#pragma unroll
    for (int j = 0; j < 4; j++) {
        int idx = base + j;
        if (idx < NBINS) g_off[idx] = run;
        run += v[j];
    }
    if (tid == 255) g_blksum[b] = src[255];
}

// Merged scan2+scan3: each block reduces its predecessors' block sums
// (<=976 ints, trivial) and applies the offset + cursor init.
__global__ __launch_bounds__(256) void scan23_kernel() {
    __shared__ int red[256];
    int b = blockIdx.x, tid = threadIdx.x;
    int part = 0;
    for (int i = tid; i < b; i += 256) part += g_blksum[i];
    red[tid] = part;
    __syncthreads();
#pragma unroll
    for (int o = 128; o > 0; o >>= 1) {
        if (tid < o) red[tid] += red[tid + o];
        __syncthreads();
    }
    int add = red[0];
#pragma unroll
    for (int j = 0; j < 4; j++) {
        int idx = b * 1024 + tid + 256 * j;
        if (idx < NBINS) {
            int o = g_off[idx] + add;
            g_off[idx] = o;
            g_cnt[idx] = o;  // cursor init
        }
    }
    if (b == 0 && tid == 0) g_off[NBINS] = TOTE;
}

__global__ void scatter_kernel(const int* __restrict__ u_rows,
                               const int* __restrict__ u_cols,
                               const float* __restrict__ u_vals,
                               const int* __restrict__ i_rows,
                               const int* __restrict__ i_cols,
                               const float* __restrict__ i_vals) {
    int e = blockIdx.x * 256 + threadIdx.x;
    if (e >= TOTE) return;
    int side = (e >= NSUP * NEDGE) ? 1 : 0;
    int ee = e - side * NSUP * NEDGE;
    const int* rows = side ? i_rows : u_rows;
    const int* cols = side ? i_cols : u_cols;
    const float* vals = side ? i_vals : u_vals;
    int s = ee / NEDGE;
    int bin = (side * NSUP + s) * NUSERS + __ldg(&rows[ee]);
    int pos = atomicAdd(&g_cnt[bin], 1);
    g_edges[pos] = make_int2(__ldg(&cols[ee]), __float_as_int(__ldg(&vals[ee])));
}

// ---------------------------------------------------------------------------
// Atomic-free gather SpMM (fp16 rows, fp32 accumulate): warp per (side,row).
// ---------------------------------------------------------------------------
__global__ __launch_bounds__(256) void gather_kernel() {
    int w = (int)((blockIdx.x * 256u + threadIdx.x) >> 5);
    if (w >= 2 * NUSERS) return;
    int lane = threadIdx.x & 31;
    int side = (w >= NUSERS) ? 1 : 0;
    int row = w - side * NUSERS;
    const uint2* src = (const uint2*)(side == 0 ? g_Ih : g_Uh);

#pragma unroll
    for (int s = 0; s < NSUP; s++) {
        int bin = (side * NSUP + s) * NUSERS + row;
        int e0 = __ldg(&g_off[bin]);
        int e1 = __ldg(&g_off[bin + 1]);
        float4 acc = make_float4(0.f, 0.f, 0.f, 0.f);
        int e = e0;
        for (; e + 2 <= e1; e += 2) {
            int2 p0 = __ldcs(&g_edges[e]);
            int2 p1 = __ldcs(&g_edges[e + 1]);
            uint2 x0 = __ldg(&src[(size_t)p0.x * 32 + lane]);
            uint2 x1 = __ldg(&src[(size_t)p1.x * 32 + lane]);
            float v0 = __int_as_float(p0.y);
            float v1 = __int_as_float(p1.y);
            float2 a0 = __half22float2(*(__half2*)&x0.x);
            float2 b0 = __half22float2(*(__half2*)&x0.y);
            float2 a1 = __half22float2(*(__half2*)&x1.x);
            float2 b1 = __half22float2(*(__half2*)&x1.y);
            acc.x += v0 * a0.x + v1 * a1.x;
            acc.y += v0 * a0.y + v1 * a1.y;
            acc.z += v0 * b0.x + v1 * b1.x;
            acc.w += v0 * b0.y + v1 * b1.y;
        }
        if (e < e1) {
            int2 p = __ldcs(&g_edges[e]);
            float v = __int_as_float(p.y);
            uint2 x = __ldg(&src[(size_t)p.x * 32 + lane]);
            float2 a = __half22float2(*(__half2*)&x.x);
            float2 b = __half22float2(*(__half2*)&x.y);
            acc.x += v * a.x;
            acc.y += v * a.y;
            acc.z += v * b.x;
            acc.w += v * b.y;
        }
        __half2 o0 = __floats2half2_rn(acc.x, acc.y);
        __half2 o1 = __floats2half2_rn(acc.z, acc.w);
        uint2 o;
        o.x = *(uint32_t*)&o0;
        o.y = *(uint32_t*)&o1;
        __stcs((uint2*)(g_Gh[side][s] + (size_t)row * 128) + lane, o);
    }
}

// ---------------------------------------------------------------------------
// fp16 ldmatrix tensor GEMM, K = 640, both sides (side = blockIdx.y).
// ---------------------------------------------------------------------------
#define RSTR 144
#define BUFB (128 * RSTR)
#define GT_TOTAL (4 * BUFB)
#define NCHUNKS 10

__device__ __forceinline__ uint32_t smem_u32(const void* p) {
    uint32_t a;
    asm("{ .reg .u64 t; cvta.to.shared.u64 t, %1; cvt.u32.u64 %0, t; }" : "=r"(a) : "l"(p));
    return a;
}
__device__ __forceinline__ void cp16(void* sdst, const void* gsrc) {
    unsigned u = (unsigned)__cvta_generic_to_shared(sdst);
    asm volatile("cp.async.cg.shared.global [%0], [%1], 16;" :: "r"(u), "l"(gsrc));
}
#define LDSM_X4(r, addr)                                                       \
    asm volatile("ldmatrix.sync.aligned.m8n8.x4.shared.b16 {%0,%1,%2,%3}, [%4];" \
                 : "=r"((r)[0]), "=r"((r)[1]), "=r"((r)[2]), "=r"((r)[3])       \
                 : "r"(addr))
#define MMA_F16(c, a, b0, b1)                                                  \
    asm volatile(                                                              \
        "mma.sync.aligned.m16n8k16.row.col.f32.f16.f16.f32 "                  \
        "{%0,%1,%2,%3}, {%4,%5,%6,%7}, {%8,%9}, {%0,%1,%2,%3};"               \
        : "+f"(c[0]), "+f"(c[1]), "+f"(c[2]), "+f"(c[3])                       \
        : "r"(a[0]), "r"(a[1]), "r"(a[2]), "r"(a[3]), "r"(b0), "r"(b1))

__global__ __launch_bounds__(256, 2) void gemm_kernel(float* __restrict__ out) {
    extern __shared__ __align__(16) char smem[];
    const int side = blockIdx.y;
    const int row0 = blockIdx.x * 128;
    const uint32_t sb = smem_u32(smem);

    const int t = threadIdx.x;
    const int wid = t >> 5;
    const int lane = t & 31;
    const int gid = lane >> 2;
    const int tig = lane & 3;
    const int wm = (wid & 3) * 32;
    const int wn = (wid >> 2) * 64;

    const uint32_t aRowByte = (uint32_t)(wm + (lane & 15)) * RSTR + (lane >> 4) * 16;
    const uint32_t bRowByte = (uint32_t)(wn + (lane >> 4) * 8 + (lane & 7)) * RSTR +
                              ((lane >> 3) & 1) * 16;

    float c[2][8][4];
#pragma unroll
    for (int mt = 0; mt < 2; mt++)
#pragma unroll
        for (int nt = 0; nt < 8; nt++)
#pragma unroll
            for (int i = 0; i < 4; i++) c[mt][nt][i] = 0.f;

    auto copy_chunk = [&](int cidx, int b) {
        int s = cidx >> 1;
        int kh = (cidx & 1) * 64;
        const __half* Asrc = g_Gh[side][s] + kh;
        const __half* Bsrc = g_Wn[s] + kh;
        char* sa = smem + b * BUFB;
        char* sbuf = smem + (2 + b) * BUFB;
#pragma unroll
        for (int i = 0; i < 4; i++) {
            int q = t + 256 * i;
            int row = q >> 3;
            int c16 = (q & 7) * 16;
            int gr = row0 + row;
            if (gr > NUSERS - 1) gr = NUSERS - 1;
            cp16(sa + row * RSTR + c16, Asrc + (size_t)gr * 128 + (c16 >> 1));
            cp16(sbuf + row * RSTR + c16, Bsrc + (size_t)row * 128 + (c16 >> 1));
        }
        asm volatile("cp.async.commit_group;" ::: "memory");
    };

    copy_chunk(0, 0);
    int buf = 0;

#pragma unroll 1
    for (int cc = 0; cc < NCHUNKS; cc++) {
        if (cc + 1 < NCHUNKS) {
            copy_chunk(cc + 1, buf ^ 1);
            asm volatile("cp.async.wait_group 1;" ::: "memory");
        } else {
            asm volatile("cp.async.wait_group 0;" ::: "memory");
        }
        __syncthreads();

        const uint32_t aBase = sb + buf * BUFB + aRowByte;
        const uint32_t bBase = sb + (2 + buf) * BUFB + bRowByte;
#pragma unroll
        for (int ks = 0; ks < 4; ks++) {
            uint32_t a[2][4], bf[4][4];
#pragma unroll
            for (int mt = 0; mt < 2; mt++)
                LDSM_X4(a[mt], aBase + mt * (16 * RSTR) + ks * 32);
#pragma unroll
            for (int nt2 = 0; nt2 < 4; nt2++)
                LDSM_X4(bf[nt2], bBase + nt2 * (16 * RSTR) + ks * 32);
#pragma unroll
            for (int mt = 0; mt < 2; mt++)
#pragma unroll
                for (int nt = 0; nt < 8; nt++) {
                    int nt2 = nt >> 1, sub = (nt & 1) * 2;
                    MMA_F16(c[mt][nt], a[mt], bf[nt2][sub], bf[nt2][sub + 1]);
                }
        }
        buf ^= 1;
        __syncthreads();
    }

    float* O = out + (size_t)side * NUSERS * 128;
#pragma unroll
    for (int mt = 0; mt < 2; mt++) {
        int r0 = row0 + wm + mt * 16 + gid;
        int r1 = r0 + 8;
#pragma unroll
        for (int nt = 0; nt < 8; nt++) {
            int cg = wn + nt * 8 + tig * 2;
            if (r0 < NUSERS)
                *(float2*)&O[(size_t)r0 * 128 + cg] =
                    make_float2(fmaxf(c[mt][nt][0], 0.f), fmaxf(c[mt][nt][1], 0.f));
            if (r1 < NUSERS)
                *(float2*)&O[(size_t)r1 * 128 + cg] =
                    make_float2(fmaxf(c[mt][nt][2], 0.f), fmaxf(c[mt][nt][3], 0.f));
        }
    }
}

// ---------------------------------------------------------------------------
// kernel_launch — 7 launches; ncu (-s 5 -c 1) lands on gather_kernel.
// ---------------------------------------------------------------------------
extern "C" void kernel_launch(void* const* d_in, const int* in_sizes, int n_in,
                              void* d_out, int out_size) {
    const float* U = (const float*)d_in[0];
    const float* It = (const float*)d_in[1];
    const float* W = (const float*)d_in[2];
    const int* u_rows = (const int*)d_in[3];
    const int* u_cols = (const int*)d_in[4];
    const float* u_vals = (const float*)d_in[5];
    const int* i_rows = (const int*)d_in[6];
    const int* i_cols = (const int*)d_in[7];
    const float* i_vals = (const float*)d_in[8];
    float* out = (float*)d_out;

    static bool smemSet = false;
    if (!smemSet) {
        cudaFuncSetAttribute(gemm_kernel, cudaFuncAttributeMaxDynamicSharedMemorySize, GT_TOTAL);
        smemSet = true;
    }

    const int eb = (TOTE + 255) / 256;

    prep_kernel<<<(2 * (NUSERS * 128 / 4) + 255) / 256, 256>>>(U, It, W);   // 0
    hist_kernel<<<eb, 256>>>(u_rows, i_rows);                               // 1
    scan1_kernel<<<NCHUNK, 256>>>();                                        // 2
    scan23_kernel<<<NCHUNK, 256>>>();                                       // 3
    scatter_kernel<<<eb, 256>>>(u_rows, u_cols, u_vals, i_rows, i_cols, i_vals); // 4
    gather_kernel<<<(2 * NUSERS * 32 + 255) / 256, 256>>>();                // 5 <- ncu
    dim3 g(MTILES, 2);
    gemm_kernel<<<g, 256, GT_TOTAL>>>(out);                                 // 6
}

// round 17
// speedup vs baseline: 1.0271x; 1.0047x over previous
#include <cuda_runtime.h>
#include <cuda_fp16.h>
#include <cstdint>
#include <cstddef>

#define NUSERS 100000
#define NITEMS 100000
#define DIN 128
#define DOUT 128
#define NSUP 5
#define NEDGE 500000
#define MTILES ((NUSERS + 127) / 128)
#define NBINS (2 * NSUP * NUSERS)
#define NCHUNK ((NBINS + 1023) / 1024)     // 977
#define TOTE (2 * NSUP * NEDGE)

// ---------------------------------------------------------------------------
// Device scratch
// ---------------------------------------------------------------------------
__device__ __half g_Wn[NSUP][DOUT * DIN];              // n-major: [s][n*128 + k]
__device__ __half g_Uh[(size_t)NUSERS * 128];
__device__ __half g_Ih[(size_t)NITEMS * 128];
__device__ __half g_Gh[2][NSUP][(size_t)NUSERS * 128]; // 256 MB gathered A
__device__ int g_cnt[NBINS];
__device__ int g_off[NBINS + 1];
__device__ int g_blksum[1024];
__device__ int2 g_edges[TOTE];

// ---------------------------------------------------------------------------
// prep: fp32->fp16 input convert + cumulative-weight fp16 repack + cnt zero.
// ---------------------------------------------------------------------------
__global__ void prep_kernel(const float* __restrict__ U, const float* __restrict__ It,
                            const float* __restrict__ w) {
    const int per = NUSERS * 128 / 4;
    int i = blockIdx.x * 256 + threadIdx.x;

    if (i < 2 * per) {  // cvt
        int side = (i >= per) ? 1 : 0;
        int j = i - side * per;
        float4 v = __ldcs((const float4*)(side ? It : U) + j);
        __half* dst = side ? g_Ih : g_Uh;
        uint2 o;
        __half2 h0 = __floats2half2_rn(v.x, v.y);
        __half2 h1 = __floats2half2_rn(v.z, v.w);
        o.x = *(uint32_t*)&h0;
        o.y = *(uint32_t*)&h1;
        __stcs((uint2*)dst + j, o);
    }
    if (i < NBINS) g_cnt[i] = 0;  // zero histogram

    if (blockIdx.x < 64) {  // wcum: 2 k-rows per block
        int k = blockIdx.x * 2 + (threadIdx.x >> 7);
        int n = threadIdx.x & 127;
        const float* p = w + ((size_t)k * DOUT + n) * NSUP;
        float acc = 0.f;
#pragma unroll
        for (int s = 0; s < NSUP; s++) {
            acc += p[s];
            g_Wn[s][n * DIN + k] = __float2half_rn(acc);
        }
    }
}

// ---------------------------------------------------------------------------
// CSR build: hist -> scan1 -> scan23 -> scatter
// ---------------------------------------------------------------------------
__global__ void hist_kernel(const int* __restrict__ u_rows,
                            const int* __restrict__ i_rows) {
    int e = blockIdx.x * 256 + threadIdx.x;
    if (e >= TOTE) return;
    int side = (e >= NSUP * NEDGE) ? 1 : 0;
    int ee = e - side * NSUP * NEDGE;
    const int* rows = side ? i_rows : u_rows;
    int s = ee / NEDGE;
    int bin = (side * NSUP + s) * NUSERS + __ldg(&rows[ee]);
    atomicAdd(&g_cnt[bin], 1);
}

__global__ __launch_bounds__(256) void scan1_kernel() {
    __shared__ int s0[256], s1[256];
    int b = blockIdx.x, tid = threadIdx.x;
    int base = b * 1024 + tid * 4;
    int v[4];
#pragma unroll
    for (int j = 0; j < 4; j++) {
        int idx = base + j;
        v[j] = (idx < NBINS) ? g_cnt[idx] : 0;
    }
    int tsum = v[0] + v[1] + v[2] + v[3];
    s0[tid] = tsum;
    __syncthreads();
    int* src = s0;
    int* dst = s1;
#pragma unroll
    for (int o = 1; o < 256; o <<= 1) {
        int x = src[tid];
        if (tid >= o) x += src[tid - o];
        __syncthreads();
        dst[tid] = x;
        __syncthreads();
        int* tmp = src; src = dst; dst = tmp;
    }
    int run = (tid == 0) ? 0 : src[tid - 1];
#pragma unroll
    for (int j = 0; j < 4; j++) {
        int idx = base + j;
        if (idx < NBINS) g_off[idx] = run;
        run += v[j];
    }
    if (tid == 255) g_blksum[b] = src[255];
}

__global__ __launch_bounds__(256) void scan23_kernel() {
    __shared__ int red[256];
    int b = blockIdx.x, tid = threadIdx.x;
    int part = 0;
    for (int i = tid; i < b; i += 256) part += g_blksum[i];
    red[tid] = part;
    __syncthreads();
#pragma unroll
    for (int o = 128; o > 0; o >>= 1) {
        if (tid < o) red[tid] += red[tid + o];
        __syncthreads();
    }
    int add = red[0];
#pragma unroll
    for (int j = 0; j < 4; j++) {
        int idx = b * 1024 + tid + 256 * j;
        if (idx < NBINS) {
            int o = g_off[idx] + add;
            g_off[idx] = o;
            g_cnt[idx] = o;  // cursor init
        }
    }
    if (b == 0 && tid == 0) g_off[NBINS] = TOTE;
}

__global__ void scatter_kernel(const int* __restrict__ u_rows,
                               const int* __restrict__ u_cols,
                               const float* __restrict__ u_vals,
                               const int* __restrict__ i_rows,
                               const int* __restrict__ i_cols,
                               const float* __restrict__ i_vals) {
    int e = blockIdx.x * 256 + threadIdx.x;
    if (e >= TOTE) return;
    int side = (e >= NSUP * NEDGE) ? 1 : 0;
    int ee = e - side * NSUP * NEDGE;
    const int* rows = side ? i_rows : u_rows;
    const int* cols = side ? i_cols : u_cols;
    const float* vals = side ? i_vals : u_vals;
    int s = ee / NEDGE;
    int bin = (side * NSUP + s) * NUSERS + __ldg(&rows[ee]);
    int pos = atomicAdd(&g_cnt[bin], 1);
    g_edges[pos] = make_int2(__ldg(&cols[ee]), __float_as_int(__ldg(&vals[ee])));
}

// ---------------------------------------------------------------------------
// Atomic-free gather SpMM (fp16 rows, fp32 accumulate): warp per (side,row).
// ---------------------------------------------------------------------------
__global__ __launch_bounds__(256) void gather_kernel() {
    int w = (int)((blockIdx.x * 256u + threadIdx.x) >> 5);
    if (w >= 2 * NUSERS) return;
    int lane = threadIdx.x & 31;
    int side = (w >= NUSERS) ? 1 : 0;
    int row = w - side * NUSERS;
    const uint2* src = (const uint2*)(side == 0 ? g_Ih : g_Uh);

#pragma unroll
    for (int s = 0; s < NSUP; s++) {
        int bin = (side * NSUP + s) * NUSERS + row;
        int e0 = __ldg(&g_off[bin]);
        int e1 = __ldg(&g_off[bin + 1]);
        float4 acc = make_float4(0.f, 0.f, 0.f, 0.f);
        int e = e0;
        for (; e + 2 <= e1; e += 2) {
            int2 p0 = __ldcs(&g_edges[e]);
            int2 p1 = __ldcs(&g_edges[e + 1]);
            uint2 x0 = __ldg(&src[(size_t)p0.x * 32 + lane]);
            uint2 x1 = __ldg(&src[(size_t)p1.x * 32 + lane]);
            float v0 = __int_as_float(p0.y);
            float v1 = __int_as_float(p1.y);
            float2 a0 = __half22float2(*(__half2*)&x0.x);
            float2 b0 = __half22float2(*(__half2*)&x0.y);
            float2 a1 = __half22float2(*(__half2*)&x1.x);
            float2 b1 = __half22float2(*(__half2*)&x1.y);
            acc.x += v0 * a0.x + v1 * a1.x;
            acc.y += v0 * a0.y + v1 * a1.y;
            acc.z += v0 * b0.x + v1 * b1.x;
            acc.w += v0 * b0.y + v1 * b1.y;
        }
        if (e < e1) {
            int2 p = __ldcs(&g_edges[e]);
            float v = __int_as_float(p.y);
            uint2 x = __ldg(&src[(size_t)p.x * 32 + lane]);
            float2 a = __half22float2(*(__half2*)&x.x);
            float2 b = __half22float2(*(__half2*)&x.y);
            acc.x += v * a.x;
            acc.y += v * a.y;
            acc.z += v * b.x;
            acc.w += v * b.y;
        }
        __half2 o0 = __floats2half2_rn(acc.x, acc.y);
        __half2 o1 = __floats2half2_rn(acc.z, acc.w);
        uint2 o;
        o.x = *(uint32_t*)&o0;
        o.y = *(uint32_t*)&o1;
        __stcs((uint2*)(g_Gh[side][s] + (size_t)row * 128) + lane, o);
    }
}

// ---------------------------------------------------------------------------
// fp16 ldmatrix tensor GEMM, K = 640, both sides (side = blockIdx.y).
// 128 thr / 4 warps (2m x 2n), block tile 128x128, warp tile 64x64
// -> MMA:LDSM byte ratio 4:1, smem crossbar no longer co-binding.
// ---------------------------------------------------------------------------
#define RSTR 144
#define BUFB (128 * RSTR)
#define GT_TOTAL (4 * BUFB)
#define NCHUNKS 10

__device__ __forceinline__ uint32_t smem_u32(const void* p) {
    uint32_t a;
    asm("{ .reg .u64 t; cvta.to.shared.u64 t, %1; cvt.u32.u64 %0, t; }" : "=r"(a) : "l"(p));
    return a;
}
__device__ __forceinline__ void cp16(void* sdst, const void* gsrc) {
    unsigned u = (unsigned)__cvta_generic_to_shared(sdst);
    asm volatile("cp.async.cg.shared.global [%0], [%1], 16;" :: "r"(u), "l"(gsrc));
}
#define LDSM_X4(r, addr)                                                       \
    asm volatile("ldmatrix.sync.aligned.m8n8.x4.shared.b16 {%0,%1,%2,%3}, [%4];" \
                 : "=r"((r)[0]), "=r"((r)[1]), "=r"((r)[2]), "=r"((r)[3])       \
                 : "r"(addr))
#define MMA_F16(c, a, b0, b1)                                                  \
    asm volatile(                                                              \
        "mma.sync.aligned.m16n8k16.row.col.f32.f16.f16.f32 "                  \
        "{%0,%1,%2,%3}, {%4,%5,%6,%7}, {%8,%9}, {%0,%1,%2,%3};"               \
        : "+f"(c[0]), "+f"(c[1]), "+f"(c[2]), "+f"(c[3])                       \
        : "r"(a[0]), "r"(a[1]), "r"(a[2]), "r"(a[3]), "r"(b0), "r"(b1))

__global__ __launch_bounds__(128, 2) void gemm_kernel(float* __restrict__ out) {
    extern __shared__ __align__(16) char smem[];
    const int side = blockIdx.y;
    const int row0 = blockIdx.x * 128;
    const uint32_t sb = smem_u32(smem);

    const int t = threadIdx.x;
    const int wid = t >> 5;
    const int lane = t & 31;
    const int gid = lane >> 2;
    const int tig = lane & 3;
    const int wm = (wid & 1) * 64;       // 2 m-warps
    const int wn = (wid >> 1) * 64;      // 2 n-warps

    // ldmatrix per-lane address components (bytes)
    const uint32_t aRowByte = (uint32_t)(wm + (lane & 15)) * RSTR + (lane >> 4) * 16;
    const uint32_t bRowByte = (uint32_t)(wn + (lane >> 4) * 8 + (lane & 7)) * RSTR +
                              ((lane >> 3) & 1) * 16;

    float c[4][8][4];
#pragma unroll
    for (int mt = 0; mt < 4; mt++)
#pragma unroll
        for (int nt = 0; nt < 8; nt++)
#pragma unroll
            for (int i = 0; i < 4; i++) c[mt][nt][i] = 0.f;

    // one chunk = 64 halves of K (s = c>>1, kh = (c&1)*64)
    auto copy_chunk = [&](int cidx, int b) {
        int s = cidx >> 1;
        int kh = (cidx & 1) * 64;
        const __half* Asrc = g_Gh[side][s] + kh;
        const __half* Bsrc = g_Wn[s] + kh;
        char* sa = smem + b * BUFB;
        char* sbuf = smem + (2 + b) * BUFB;
#pragma unroll
        for (int i = 0; i < 8; i++) {
            int q = t + 128 * i;            // 0..1023
            int row = q >> 3;               // 0..127
            int c16 = (q & 7) * 16;         // byte col (8 halves per quad)
            int gr = row0 + row;
            if (gr > NUSERS - 1) gr = NUSERS - 1;  // clamp; stores guarded
            cp16(sa + row * RSTR + c16, Asrc + (size_t)gr * 128 + (c16 >> 1));
            cp16(sbuf + row * RSTR + c16, Bsrc + (size_t)row * 128 + (c16 >> 1));
        }
        asm volatile("cp.async.commit_group;" ::: "memory");
    };

    copy_chunk(0, 0);
    int buf = 0;

#pragma unroll 1
    for (int cc = 0; cc < NCHUNKS; cc++) {
        if (cc + 1 < NCHUNKS) {
            copy_chunk(cc + 1, buf ^ 1);
            asm volatile("cp.async.wait_group 1;" ::: "memory");
        } else {
            asm volatile("cp.async.wait_group 0;" ::: "memory");
        }
        __syncthreads();

        const uint32_t aBase = sb + buf * BUFB + aRowByte;
        const uint32_t bBase = sb + (2 + buf) * BUFB + bRowByte;
#pragma unroll
        for (int ks = 0; ks < 4; ks++) {      // four k16 steps per chunk
            uint32_t a[4][4], bf[4][4];
#pragma unroll
            for (int mt = 0; mt < 4; mt++)
                LDSM_X4(a[mt], aBase + mt * (16 * RSTR) + ks * 32);
#pragma unroll
            for (int nt2 = 0; nt2 < 4; nt2++)
                LDSM_X4(bf[nt2], bBase + nt2 * (16 * RSTR) + ks * 32);
#pragma unroll
            for (int mt = 0; mt < 4; mt++)
#pragma unroll
                for (int nt = 0; nt < 8; nt++) {
                    int nt2 = nt >> 1, sub = (nt & 1) * 2;
                    MMA_F16(c[mt][nt], a[mt], bf[nt2][sub], bf[nt2][sub + 1]);
                }
        }
        buf ^= 1;
        __syncthreads();
    }

    float* O = out + (size_t)side * NUSERS * 128;
#pragma unroll
    for (int mt = 0; mt < 4; mt++) {
        int r0 = row0 + wm + mt * 16 + gid;
        int r1 = r0 + 8;
#pragma unroll
        for (int nt = 0; nt < 8; nt++) {
            int cg = wn + nt * 8 + tig * 2;
            if (r0 < NUSERS)
                *(float2*)&O[(size_t)r0 * 128 + cg] =
                    make_float2(fmaxf(c[mt][nt][0], 0.f), fmaxf(c[mt][nt][1], 0.f));
            if (r1 < NUSERS)
                *(float2*)&O[(size_t)r1 * 128 + cg] =
                    make_float2(fmaxf(c[mt][nt][2], 0.f), fmaxf(c[mt][nt][3], 0.f));
        }
    }
}

// ---------------------------------------------------------------------------
// kernel_launch — 7 launches.
// ---------------------------------------------------------------------------
extern "C" void kernel_launch(void* const* d_in, const int* in_sizes, int n_in,
                              void* d_out, int out_size) {
    const float* U = (const float*)d_in[0];
    const float* It = (const float*)d_in[1];
    const float* W = (const float*)d_in[2];
    const int* u_rows = (const int*)d_in[3];
    const int* u_cols = (const int*)d_in[4];
    const float* u_vals = (const float*)d_in[5];
    const int* i_rows = (const int*)d_in[6];
    const int* i_cols = (const int*)d_in[7];
    const float* i_vals = (const float*)d_in[8];
    float* out = (float*)d_out;

    static bool smemSet = false;
    if (!smemSet) {
        cudaFuncSetAttribute(gemm_kernel, cudaFuncAttributeMaxDynamicSharedMemorySize, GT_TOTAL);
        smemSet = true;
    }

    const int eb = (TOTE + 255) / 256;

    prep_kernel<<<(2 * (NUSERS * 128 / 4) + 255) / 256, 256>>>(U, It, W);
    hist_kernel<<<eb, 256>>>(u_rows, i_rows);
    scan1_kernel<<<NCHUNK, 256>>>();
    scan23_kernel<<<NCHUNK, 256>>>();
    scatter_kernel<<<eb, 256>>>(u_rows, u_cols, u_vals, i_rows, i_cols, i_vals);
    gather_kernel<<<(2 * NUSERS * 32 + 255) / 256, 256>>>();
    dim3 g(MTILES, 2);
    gemm_kernel<<<g, 128, GT_TOTAL>>>(out);
}